// round 6
// baseline (speedup 1.0000x reference)
#include <cuda_runtime.h>
#include <cuda_bf16.h>
#include <cuda_fp8.h>
#include <cstdint>

#define MDIM 16384
#define KDIM 2048
#define NDIM 2048

#define BM 128
#define BN 128
#define BK 64                // fp8 elems per K-tile = 64 bytes/row
#define KITERS (KDIM / BK)   // 32
#define STAGES 4
#define ROWB 80              // padded row pitch (64B data + 16B pad; 5*16B coprime 8 banks)
#define STAGE_BYTES (2 * BM * ROWB)                 // A tile + B tile = 20480
#define GEMM_SMEM (STAGES * STAGE_BYTES + 32)       // + 8-float reduce scratch

#define NPART 1024           // amax partial count

// ---------------- device scratch (allocation-free rule) ----------------------
__device__ __align__(16) uint8_t g_qa[(size_t)MDIM * KDIM]; // 32 MB fp8
__device__ __align__(16) uint8_t g_qb[(size_t)NDIM * KDIM]; // 4 MB fp8
__device__ float g_partial[NPART];

// ---------------- helpers ----------------------------------------------------
__device__ __forceinline__ uint32_t smem_u32(const void* p) {
    uint32_t a;
    asm("{ .reg .u64 t; cvta.to.shared.u64 t, %1; cvt.u32.u64 %0, t; }"
        : "=r"(a) : "l"(p));
    return a;
}

#define CP_ASYNC16(smem, gptr) \
    asm volatile("cp.async.cg.shared.global [%0], [%1], 16;" \
                 :: "r"(smem), "l"(gptr) : "memory")
#define CP_COMMIT() asm volatile("cp.async.commit_group;" ::: "memory")
#define CP_WAIT(n)  asm volatile("cp.async.wait_group %0;" :: "n"(n) : "memory")

#define LDSM_X4(r0, r1, r2, r3, addr) \
    asm volatile("ldmatrix.sync.aligned.m8n8.x4.shared.b16 {%0,%1,%2,%3}, [%4];" \
                 : "=r"(r0), "=r"(r1), "=r"(r2), "=r"(r3) : "r"(addr))

// fp8 e4m3 MMA: m16n8k32, fragment layout == bf16 m16n8k16 with b16 elem = 2 fp8
#define MMA16832(c, a, b0, b1) \
    asm volatile("mma.sync.aligned.m16n8k32.row.col.f32.e4m3.e4m3.f32 " \
                 "{%0,%1,%2,%3}, {%4,%5,%6,%7}, {%8,%9}, {%0,%1,%2,%3};" \
                 : "+f"((c)[0]), "+f"((c)[1]), "+f"((c)[2]), "+f"((c)[3]) \
                 : "r"((a)[0]), "r"((a)[1]), "r"((a)[2]), "r"((a)[3]), \
                   "r"(b0), "r"(b1))

// ---------------- fp8 conversion ---------------------------------------------
__device__ __forceinline__ uint8_t to_e4m3(float v) {
    __nv_fp8_e4m3 q(v);                 // RN + satfinite == clip(+-448) + round in ref
    return *reinterpret_cast<uint8_t*>(&q);
}

// ---------------- launch 1: quantize weights (independent) -------------------
__global__ void quant_b_kernel(const float* __restrict__ w) {
    int i = blockIdx.x * blockDim.x + threadIdx.x;  // float4 index
    float4 v = ((const float4*)w)[i];
    // weight values already on the fp8 grid -> conversion exact
    uint32_t o = (uint32_t)to_e4m3(v.x)
               | ((uint32_t)to_e4m3(v.y) << 8)
               | ((uint32_t)to_e4m3(v.z) << 16)
               | ((uint32_t)to_e4m3(v.w) << 24);
    ((uint32_t*)g_qb)[i] = o;
}

// ---------------- launch 2: per-block amax partials (no init needed) ---------
__global__ void amax_partial_kernel(const float* __restrict__ x, int n4) {
    const float4* x4 = (const float4*)x;
    float m = 0.0f;
    for (int i = blockIdx.x * blockDim.x + threadIdx.x; i < n4; i += gridDim.x * blockDim.x) {
        float4 v = x4[i];
        m = fmaxf(m, fmaxf(fmaxf(fabsf(v.x), fabsf(v.y)), fmaxf(fabsf(v.z), fabsf(v.w))));
    }
    #pragma unroll
    for (int o = 16; o; o >>= 1) m = fmaxf(m, __shfl_xor_sync(0xFFFFFFFFu, m, o));
    __shared__ float sm[8];
    if ((threadIdx.x & 31) == 0) sm[threadIdx.x >> 5] = m;
    __syncthreads();
    if (threadIdx.x == 0) {
        #pragma unroll
        for (int w = 1; w < 8; w++) m = fmaxf(m, sm[w]);
        g_partial[blockIdx.x] = m;      // plain overwrite: deterministic per call
    }
}

// ---------------- launch 3: quantize activations (inline partial-reduce) -----
__global__ void quant_a_kernel(const float* __restrict__ x) {
    float m = 0.0f;
    #pragma unroll
    for (int i = 0; i < NPART / 256; i++)
        m = fmaxf(m, g_partial[threadIdx.x + i * 256]);
    #pragma unroll
    for (int o = 16; o; o >>= 1) m = fmaxf(m, __shfl_xor_sync(0xFFFFFFFFu, m, o));
    __shared__ float sm[8];
    if ((threadIdx.x & 31) == 0) sm[threadIdx.x >> 5] = m;
    __syncthreads();
    m = sm[0];
    #pragma unroll
    for (int w = 1; w < 8; w++) m = fmaxf(m, sm[w]);
    float scale = 448.0f / fmaxf(m, 1e-12f);

    int base = blockIdx.x * blockDim.x + threadIdx.x;
    const int stride = 2048 * 256;
    #pragma unroll 4
    for (int it = 0; it < 16; it++) {
        int i = base + it * stride;
        float4 v = ((const float4*)x)[i];
        uint32_t o = (uint32_t)to_e4m3(v.x * scale)
                   | ((uint32_t)to_e4m3(v.y * scale) << 8)
                   | ((uint32_t)to_e4m3(v.z * scale) << 16)
                   | ((uint32_t)to_e4m3(v.w * scale) << 24);
        ((uint32_t*)g_qa)[i] = o;
    }
}

// ---------------- launch 4: GEMM (fp8 mma.sync, cp.async pipeline) -----------
// 256 threads = 8 warps (4x2), warp tile 32x64, CTA tile 128x128, 4 stages.

__global__ __launch_bounds__(256, 2)
void gemm_kernel(const float* __restrict__ wscale, const float* __restrict__ bias,
                 float* __restrict__ out) {
    extern __shared__ char smem[];
    const uint32_t s0 = smem_u32(smem);
    float* sred = (float*)(smem + STAGES * STAGE_BYTES);

    const int tid = threadIdx.x;
    const int wid = tid >> 5, lane = tid & 31;
    const int warp_m = wid >> 1, warp_n = wid & 1;   // 4 x 2 warps, 32x64 tiles
    const int ntile = blockIdx.x, mtile = blockIdx.y;
    const int quad = lane >> 3, l8 = lane & 7;

    // per-thread cp.async global base pointers (row/chunk folded in once)
    const int c0 = tid, c1 = tid + 256;
    const int ar0 = c0 >> 2, ac0 = c0 & 3;
    const int ar1 = c1 >> 2, ac1 = c1 & 3;
    const uint8_t* gA0 = g_qa + (size_t)mtile * BM * KDIM + (size_t)ar0 * KDIM + ac0 * 16;
    const uint8_t* gA1 = g_qa + (size_t)mtile * BM * KDIM + (size_t)ar1 * KDIM + ac1 * 16;
    const uint8_t* gB0 = g_qb + (size_t)ntile * BN * KDIM + (size_t)ar0 * KDIM + ac0 * 16;
    const uint8_t* gB1 = g_qb + (size_t)ntile * BN * KDIM + (size_t)ar1 * KDIM + ac1 * 16;
    const uint32_t sOff0 = (uint32_t)(ar0 * ROWB + ac0 * 16);
    const uint32_t sOff1 = (uint32_t)(ar1 * ROWB + ac1 * 16) + (uint32_t)(BM * ROWB);
    // note: sOff1 carries the B-tile base so A uses sOff1-B? NO — keep separate:
    const uint32_t sA0 = (uint32_t)(ar0 * ROWB + ac0 * 16);
    const uint32_t sA1 = (uint32_t)(ar1 * ROWB + ac1 * 16);

    // amax partial reduce (overlapped with prologue)
    float pm = fmaxf(fmaxf(g_partial[tid], g_partial[tid + 256]),
                     fmaxf(g_partial[tid + 512], g_partial[tid + 768]));
    #pragma unroll
    for (int o = 16; o; o >>= 1) pm = fmaxf(pm, __shfl_xor_sync(0xFFFFFFFFu, pm, o));
    if (lane == 0) sred[wid] = pm;   // visible after first mainloop __syncthreads

    // ldmatrix per-thread base offsets within a stage
    uint32_t aoff[2], boff[4];
    #pragma unroll
    for (int i = 0; i < 2; i++)
        aoff[i] = (uint32_t)((warp_m * 32 + i * 16 + (quad & 1) * 8 + l8) * ROWB
                             + (quad >> 1) * 16);
    #pragma unroll
    for (int j = 0; j < 4; j++)
        boff[j] = (uint32_t)(BM * ROWB
                             + (warp_n * 64 + j * 16 + (quad >> 1) * 8 + l8) * ROWB
                             + (quad & 1) * 16);

    float acc[2][8][4];
    #pragma unroll
    for (int mi = 0; mi < 2; mi++)
        #pragma unroll
        for (int ni = 0; ni < 8; ni++)
            #pragma unroll
            for (int r = 0; r < 4; r++) acc[mi][ni][r] = 0.0f;

    // ---- prologue: fill STAGES-1 stages
    #pragma unroll
    for (int st = 0; st < STAGES - 1; st++) {
        uint32_t sb = s0 + st * STAGE_BYTES;
        uint32_t ko = (uint32_t)st << 6;
        CP_ASYNC16(sb + sA0, gA0 + ko);
        CP_ASYNC16(sb + sA1, gA1 + ko);
        CP_ASYNC16(sb + (uint32_t)(BM * ROWB) + sA0, gB0 + ko);
        CP_ASYNC16(sb + (uint32_t)(BM * ROWB) + sA1, gB1 + ko);
        CP_COMMIT();
    }

    // ---- mainloop (single barrier per iteration, pow2 stage math)
    #pragma unroll 1
    for (int it = 0; it < KITERS; ++it) {
        CP_WAIT(STAGES - 2);
        __syncthreads();

        uint32_t sb = s0 + (uint32_t)(it & 3) * STAGE_BYTES;

        // 1) issue all fragment loads for both k32 steps (12 LDSM.x4)
        uint32_t a[2][2][4], b[2][4][4];
        #pragma unroll
        for (int s = 0; s < 2; s++) {
            #pragma unroll
            for (int i = 0; i < 2; i++)
                LDSM_X4(a[s][i][0], a[s][i][1], a[s][i][2], a[s][i][3],
                        sb + aoff[i] + s * 32);
            #pragma unroll
            for (int j = 0; j < 4; j++)
                LDSM_X4(b[s][j][0], b[s][j][1], b[s][j][2], b[s][j][3],
                        sb + boff[j] + s * 32);
        }

        // 2) prefetch stage it+3 (overwrites buffer last read at it-1)
        {
            int lt = it + STAGES - 1;
            if (lt < KITERS) {
                uint32_t psb = s0 + (uint32_t)(lt & 3) * STAGE_BYTES;
                uint32_t ko = (uint32_t)lt << 6;
                CP_ASYNC16(psb + sA0, gA0 + ko);
                CP_ASYNC16(psb + sA1, gA1 + ko);
                CP_ASYNC16(psb + (uint32_t)(BM * ROWB) + sA0, gB0 + ko);
                CP_ASYNC16(psb + (uint32_t)(BM * ROWB) + sA1, gB1 + ko);
            }
            CP_COMMIT();   // keep wait_group counting uniform at the tail
        }

        // 3) clean MMA burst (32 MMAs); LDSM latency drains behind the first few
        #pragma unroll
        for (int s = 0; s < 2; s++)
            #pragma unroll
            for (int mi = 0; mi < 2; mi++)
                #pragma unroll
                for (int ni = 0; ni < 8; ni++)
                    MMA16832(acc[mi][ni], a[s][mi], b[s][ni >> 1][(ni & 1) * 2],
                             b[s][ni >> 1][(ni & 1) * 2 + 1]);
    }

    // ---- epilogue: out = acc * (a_scale * w_scale) + bias
    float amax = sred[0];
    #pragma unroll
    for (int w = 1; w < 8; w++) amax = fmaxf(amax, sred[w]);
    float comb = (fmaxf(amax, 1e-12f) / 448.0f) * wscale[0];

    const int gid = lane >> 2;
    const int lq = lane & 3;
    #pragma unroll
    for (int mi = 0; mi < 2; mi++) {
        int r0 = mtile * BM + warp_m * 32 + mi * 16 + gid;
        #pragma unroll
        for (int ni = 0; ni < 8; ni++) {
            int colg = ntile * BN + warp_n * 64 + ni * 8 + lq * 2;
            float2 bb = *(const float2*)(bias + colg);
            float2 o0, o1;
            o0.x = acc[mi][ni][0] * comb + bb.x;
            o0.y = acc[mi][ni][1] * comb + bb.y;
            o1.x = acc[mi][ni][2] * comb + bb.x;
            o1.y = acc[mi][ni][3] * comb + bb.y;
            *(float2*)(out + (size_t)r0 * NDIM + colg) = o0;
            *(float2*)(out + (size_t)(r0 + 8) * NDIM + colg) = o1;
        }
    }
}

// ---------------- launch 5: keep per-call launch count stable ----------------
__global__ void noop_kernel() {}

// ---------------- launch -----------------------------------------------------
extern "C" void kernel_launch(void* const* d_in, const int* in_sizes, int n_in,
                              void* d_out, int out_size) {
    const float* input = nullptr;
    const float* qweight = nullptr;
    const float* wscale = nullptr;
    const float* bias = nullptr;
    for (int i = 0; i < n_in; i++) {
        long long s = in_sizes[i];
        if (s == (long long)MDIM * KDIM) input = (const float*)d_in[i];
        else if (s == (long long)NDIM * KDIM) qweight = (const float*)d_in[i];
        else if (s == 1) wscale = (const float*)d_in[i];
        else if (s == NDIM) bias = (const float*)d_in[i];
    }
    float* out = (float*)d_out;

    cudaFuncSetAttribute(gemm_kernel, cudaFuncAttributeMaxDynamicSharedMemorySize,
                         GEMM_SMEM);

    quant_b_kernel<<<NDIM * KDIM / 4 / 256, 256>>>(qweight);
    amax_partial_kernel<<<NPART, 256>>>(input, MDIM * KDIM / 4);
    quant_a_kernel<<<2048, 256>>>(input);

    dim3 grid(NDIM / BN, MDIM / BM);   // ntile fastest: weight tiles stay L2-resident
    gemm_kernel<<<grid, 256, GEMM_SMEM>>>(wscale, bias, out);
    noop_kernel<<<1, 1>>>();
}

// round 8
// speedup vs baseline: 1.7513x; 1.7513x over previous
#include <cuda_runtime.h>
#include <cuda_bf16.h>
#include <cuda_fp8.h>
#include <cstdint>

#define MDIM 16384
#define KDIM 2048
#define NDIM 2048

#define BM 128
#define BN 128
#define BK 128               // fp8 elems per K-tile = 128 bytes/row
#define KITERS (KDIM / BK)   // 16
#define STAGES 3
#define ROWB 144             // padded row pitch (128B data + 16B pad; 9*16B coprime 8 banks)
#define STAGE_BYTES (2 * BM * ROWB)                 // A tile + B tile = 36864
#define GEMM_SMEM (STAGES * STAGE_BYTES + 32)       // 110624 (+ 8-float reduce scratch)

#define NPART 1024           // amax partial count

// ---------------- device scratch (allocation-free rule) ----------------------
__device__ __align__(16) uint8_t g_qa[(size_t)MDIM * KDIM]; // 32 MB fp8
__device__ __align__(16) uint8_t g_qb[(size_t)NDIM * KDIM]; // 4 MB fp8
__device__ float g_partial[NPART];

// ---------------- helpers ----------------------------------------------------
__device__ __forceinline__ uint32_t smem_u32(const void* p) {
    uint32_t a;
    asm("{ .reg .u64 t; cvta.to.shared.u64 t, %1; cvt.u32.u64 %0, t; }"
        : "=r"(a) : "l"(p));
    return a;
}

#define CP_ASYNC16(smem, gptr) \
    asm volatile("cp.async.cg.shared.global [%0], [%1], 16;" \
                 :: "r"(smem), "l"(gptr) : "memory")
#define CP_COMMIT() asm volatile("cp.async.commit_group;" ::: "memory")
#define CP_WAIT(n)  asm volatile("cp.async.wait_group %0;" :: "n"(n) : "memory")

#define LDSM_X4(r0, r1, r2, r3, addr) \
    asm volatile("ldmatrix.sync.aligned.m8n8.x4.shared.b16 {%0,%1,%2,%3}, [%4];" \
                 : "=r"(r0), "=r"(r1), "=r"(r2), "=r"(r3) : "r"(addr))

// fp8 e4m3 MMA: m16n8k32, fragment layout == bf16 m16n8k16 with b16 elem = 2 fp8
#define MMA16832(c, a, b0, b1) \
    asm volatile("mma.sync.aligned.m16n8k32.row.col.f32.e4m3.e4m3.f32 " \
                 "{%0,%1,%2,%3}, {%4,%5,%6,%7}, {%8,%9}, {%0,%1,%2,%3};" \
                 : "+f"((c)[0]), "+f"((c)[1]), "+f"((c)[2]), "+f"((c)[3]) \
                 : "r"((a)[0]), "r"((a)[1]), "r"((a)[2]), "r"((a)[3]), \
                   "r"(b0), "r"(b1))

// ---------------- fp8 conversion ---------------------------------------------
__device__ __forceinline__ uint8_t to_e4m3(float v) {
    __nv_fp8_e4m3 q(v);                 // RN + satfinite == clip(+-448) + round in ref
    return *reinterpret_cast<uint8_t*>(&q);
}

// ---------------- launch 1: quantize weights (independent) -------------------
__global__ void quant_b_kernel(const float* __restrict__ w) {
    int i = blockIdx.x * blockDim.x + threadIdx.x;  // float4 index
    float4 v = ((const float4*)w)[i];
    // weight values already on the fp8 grid -> conversion exact
    uint32_t o = (uint32_t)to_e4m3(v.x)
               | ((uint32_t)to_e4m3(v.y) << 8)
               | ((uint32_t)to_e4m3(v.z) << 16)
               | ((uint32_t)to_e4m3(v.w) << 24);
    ((uint32_t*)g_qb)[i] = o;
}

// ---------------- launch 2: per-block amax partials (no init needed) ---------
__global__ void amax_partial_kernel(const float* __restrict__ x, int n4) {
    const float4* x4 = (const float4*)x;
    float m = 0.0f;
    for (int i = blockIdx.x * blockDim.x + threadIdx.x; i < n4; i += gridDim.x * blockDim.x) {
        float4 v = x4[i];
        m = fmaxf(m, fmaxf(fmaxf(fabsf(v.x), fabsf(v.y)), fmaxf(fabsf(v.z), fabsf(v.w))));
    }
    #pragma unroll
    for (int o = 16; o; o >>= 1) m = fmaxf(m, __shfl_xor_sync(0xFFFFFFFFu, m, o));
    __shared__ float sm[8];
    if ((threadIdx.x & 31) == 0) sm[threadIdx.x >> 5] = m;
    __syncthreads();
    if (threadIdx.x == 0) {
        #pragma unroll
        for (int w = 1; w < 8; w++) m = fmaxf(m, sm[w]);
        g_partial[blockIdx.x] = m;      // plain overwrite: deterministic per call
    }
}

// ---------------- launch 3: quantize activations (inline partial-reduce) -----
__global__ void quant_a_kernel(const float* __restrict__ x) {
    float m = 0.0f;
    #pragma unroll
    for (int i = 0; i < NPART / 256; i++)
        m = fmaxf(m, g_partial[threadIdx.x + i * 256]);
    #pragma unroll
    for (int o = 16; o; o >>= 1) m = fmaxf(m, __shfl_xor_sync(0xFFFFFFFFu, m, o));
    __shared__ float sm[8];
    if ((threadIdx.x & 31) == 0) sm[threadIdx.x >> 5] = m;
    __syncthreads();
    m = sm[0];
    #pragma unroll
    for (int w = 1; w < 8; w++) m = fmaxf(m, sm[w]);
    float scale = 448.0f / fmaxf(m, 1e-12f);

    int base = blockIdx.x * blockDim.x + threadIdx.x;
    const int stride = 2048 * 256;
    #pragma unroll 4
    for (int it = 0; it < 16; it++) {
        int i = base + it * stride;
        float4 v = ((const float4*)x)[i];
        uint32_t o = (uint32_t)to_e4m3(v.x * scale)
                   | ((uint32_t)to_e4m3(v.y * scale) << 8)
                   | ((uint32_t)to_e4m3(v.z * scale) << 16)
                   | ((uint32_t)to_e4m3(v.w * scale) << 24);
        ((uint32_t*)g_qa)[i] = o;
    }
}

// ---------------- launch 4: GEMM (fp8 mma.sync, cp.async pipeline) -----------
// 256 threads = 8 warps (4x2), warp tile 32x64, CTA tile 128x128.
// BK=128: 16 K-iters, 64 MMAs + 1 barrier per iter, 3 SMEM stages.

__global__ __launch_bounds__(256, 2)
void gemm_kernel(const float* __restrict__ wscale, const float* __restrict__ bias,
                 float* __restrict__ out) {
    extern __shared__ char smem[];
    const uint32_t s0 = smem_u32(smem);
    float* sred = (float*)(smem + STAGES * STAGE_BYTES);

    const int tid = threadIdx.x;
    const int wid = tid >> 5, lane = tid & 31;
    const int warp_m = wid >> 1, warp_n = wid & 1;   // 4 x 2 warps, 32x64 tiles
    const int ntile = blockIdx.x, mtile = blockIdx.y;
    const int quad = lane >> 3, l8 = lane & 7;

    // cp.async mapping: tile = 128 rows x 8 (16B chunks) = 1024 chunks; 4/thread/tile
    int row_[4], chk_[4];
    uint32_t sOf_[4];
    #pragma unroll
    for (int p = 0; p < 4; p++) {
        int c = tid + p * 256;
        row_[p] = c >> 3; chk_[p] = c & 7;
        sOf_[p] = (uint32_t)(row_[p] * ROWB + chk_[p] * 16);
    }
    const uint8_t* gA[4];
    const uint8_t* gB[4];
    #pragma unroll
    for (int p = 0; p < 4; p++) {
        gA[p] = g_qa + (size_t)mtile * BM * KDIM + (size_t)row_[p] * KDIM + chk_[p] * 16;
        gB[p] = g_qb + (size_t)ntile * BN * KDIM + (size_t)row_[p] * KDIM + chk_[p] * 16;
    }

    // amax partial reduce (overlapped with prologue)
    float pm = fmaxf(fmaxf(g_partial[tid], g_partial[tid + 256]),
                     fmaxf(g_partial[tid + 512], g_partial[tid + 768]));
    #pragma unroll
    for (int o = 16; o; o >>= 1) pm = fmaxf(pm, __shfl_xor_sync(0xFFFFFFFFu, pm, o));
    if (lane == 0) sred[wid] = pm;   // visible after first mainloop __syncthreads

    // ldmatrix per-thread base offsets within a stage
    uint32_t aoff[2], boff[4];
    #pragma unroll
    for (int i = 0; i < 2; i++)
        aoff[i] = (uint32_t)((warp_m * 32 + i * 16 + (quad & 1) * 8 + l8) * ROWB
                             + (quad >> 1) * 16);
    #pragma unroll
    for (int j = 0; j < 4; j++)
        boff[j] = (uint32_t)(BM * ROWB
                             + (warp_n * 64 + j * 16 + (quad >> 1) * 8 + l8) * ROWB
                             + (quad & 1) * 16);

    float acc[2][8][4];
    #pragma unroll
    for (int mi = 0; mi < 2; mi++)
        #pragma unroll
        for (int ni = 0; ni < 8; ni++)
            #pragma unroll
            for (int r = 0; r < 4; r++) acc[mi][ni][r] = 0.0f;

    // ---- prologue: fill STAGES-1 stages
    #pragma unroll
    for (int st = 0; st < STAGES - 1; st++) {
        uint32_t sb = s0 + st * STAGE_BYTES;
        uint32_t ko = (uint32_t)st << 7;
        #pragma unroll
        for (int p = 0; p < 4; p++) {
            CP_ASYNC16(sb + sOf_[p], gA[p] + ko);
            CP_ASYNC16(sb + (uint32_t)(BM * ROWB) + sOf_[p], gB[p] + ko);
        }
        CP_COMMIT();
    }

    // ---- mainloop: single barrier per iteration, wrap-increment stage index
    int cs = 0;                   // current stage
    int ps = STAGES - 1;          // prefetch stage
    #pragma unroll 1
    for (int it = 0; it < KITERS; ++it) {
        CP_WAIT(STAGES - 2);
        __syncthreads();

        uint32_t sb = s0 + (uint32_t)cs * STAGE_BYTES;

        {   // prefetch stage it+2 (overwrites buffer last read at it-1)
            int lt = it + STAGES - 1;
            if (lt < KITERS) {
                uint32_t psb = s0 + (uint32_t)ps * STAGE_BYTES;
                uint32_t ko = (uint32_t)lt << 7;
                #pragma unroll
                for (int p = 0; p < 4; p++) {
                    CP_ASYNC16(psb + sOf_[p], gA[p] + ko);
                    CP_ASYNC16(psb + (uint32_t)(BM * ROWB) + sOf_[p], gB[p] + ko);
                }
            }
            CP_COMMIT();   // keep wait_group counting uniform at the tail
        }

        // 4 k32 steps; fragments live for one step only (keeps regs <= 128)
        #pragma unroll
        for (int s = 0; s < 4; s++) {
            uint32_t a[2][4], b[4][4];
            #pragma unroll
            for (int i = 0; i < 2; i++)
                LDSM_X4(a[i][0], a[i][1], a[i][2], a[i][3], sb + aoff[i] + s * 32);
            #pragma unroll
            for (int j = 0; j < 4; j++)
                LDSM_X4(b[j][0], b[j][1], b[j][2], b[j][3], sb + boff[j] + s * 32);
            #pragma unroll
            for (int mi = 0; mi < 2; mi++)
                #pragma unroll
                for (int ni = 0; ni < 8; ni++)
                    MMA16832(acc[mi][ni], a[mi], b[ni >> 1][(ni & 1) * 2],
                             b[ni >> 1][(ni & 1) * 2 + 1]);
        }

        cs = (cs == STAGES - 1) ? 0 : cs + 1;
        ps = (ps == STAGES - 1) ? 0 : ps + 1;
    }

    // ---- epilogue: out = acc * (a_scale * w_scale) + bias
    float amax = sred[0];
    #pragma unroll
    for (int w = 1; w < 8; w++) amax = fmaxf(amax, sred[w]);
    float comb = (fmaxf(amax, 1e-12f) / 448.0f) * wscale[0];

    const int gid = lane >> 2;
    const int lq = lane & 3;
    #pragma unroll
    for (int mi = 0; mi < 2; mi++) {
        int r0 = mtile * BM + warp_m * 32 + mi * 16 + gid;
        #pragma unroll
        for (int ni = 0; ni < 8; ni++) {
            int colg = ntile * BN + warp_n * 64 + ni * 8 + lq * 2;
            float2 bb = *(const float2*)(bias + colg);
            float2 o0, o1;
            o0.x = acc[mi][ni][0] * comb + bb.x;
            o0.y = acc[mi][ni][1] * comb + bb.y;
            o1.x = acc[mi][ni][2] * comb + bb.x;
            o1.y = acc[mi][ni][3] * comb + bb.y;
            *(float2*)(out + (size_t)r0 * NDIM + colg) = o0;
            *(float2*)(out + (size_t)(r0 + 8) * NDIM + colg) = o1;
        }
    }
}

// ---------------- launch 5: keep per-call launch count stable ----------------
__global__ void noop_kernel() {}

// ---------------- launch -----------------------------------------------------
extern "C" void kernel_launch(void* const* d_in, const int* in_sizes, int n_in,
                              void* d_out, int out_size) {
    const float* input = nullptr;
    const float* qweight = nullptr;
    const float* wscale = nullptr;
    const float* bias = nullptr;
    for (int i = 0; i < n_in; i++) {
        long long s = in_sizes[i];
        if (s == (long long)MDIM * KDIM) input = (const float*)d_in[i];
        else if (s == (long long)NDIM * KDIM) qweight = (const float*)d_in[i];
        else if (s == 1) wscale = (const float*)d_in[i];
        else if (s == NDIM) bias = (const float*)d_in[i];
    }
    float* out = (float*)d_out;

    cudaFuncSetAttribute(gemm_kernel, cudaFuncAttributeMaxDynamicSharedMemorySize,
                         GEMM_SMEM);

    quant_b_kernel<<<NDIM * KDIM / 4 / 256, 256>>>(qweight);
    amax_partial_kernel<<<NPART, 256>>>(input, MDIM * KDIM / 4);
    quant_a_kernel<<<2048, 256>>>(input);

    dim3 grid(NDIM / BN, MDIM / BM);   // ntile fastest: weight tiles stay L2-resident
    gemm_kernel<<<grid, 256, GEMM_SMEM>>>(wscale, bias, out);
    noop_kernel<<<1, 1>>>();
}